// round 2
// baseline (speedup 1.0000x reference)
#include <cuda_runtime.h>
#include <math_constants.h>

// SpatialArgmax2d: per (B,N) 128x128 heatmap, argmax + sub-pixel parabolic fit.
// Input:  (B, N, H, W) fp32, B*N = 2048 maps of 16384 floats (64 KB each).
// Output: (B, N, 2) fp32 -> (x + dx, y + dy).
//
// One CTA per map, 256 threads x 16 float4. Per-vector: fmaxf tree (3 FMNMX)
// + one select tracking the vec index only; two independent accumulators to
// break the serial dependency chain. Component decoded once at the end by
// re-reading the winning float4 (L2 hit). First-index argmax semantics are
// preserved exactly.

#define HH 128
#define WW 128
#define TPB 256
#define ELEMS_PER_MAP (HH * WW)              // 16384
#define VEC4_PER_MAP (ELEMS_PER_MAP / 4)     // 4096
#define VEC4_PER_THREAD (VEC4_PER_MAP / TPB) // 16

__global__ __launch_bounds__(TPB) void spatial_argmax2d_kernel(
    const float* __restrict__ in, float* __restrict__ out)
{
    const int map = blockIdx.x;
    const float* __restrict__ m = in + (size_t)map * ELEMS_PER_MAP;
    const float4* __restrict__ m4 = reinterpret_cast<const float4*>(m);
    const int tid = threadIdx.x;

    // Two independent (value, vec-index) accumulators; strict '>' keeps the
    // earliest vec within each chain (k increases => i4 increases).
    float best0 = -CUDART_INF_F, best1 = -CUDART_INF_F;
    int   vec0  = 0,             vec1  = 0;

    #pragma unroll
    for (int k = 0; k < VEC4_PER_THREAD; k += 2) {
        const int ia = tid + k * TPB;
        const int ib = tid + (k + 1) * TPB;
        const float4 va = m4[ia];
        const float4 vb = m4[ib];
        const float ma = fmaxf(fmaxf(va.x, va.y), fmaxf(va.z, va.w));
        const float mb = fmaxf(fmaxf(vb.x, vb.y), fmaxf(vb.z, vb.w));
        if (ma > best0) { best0 = ma; vec0 = ia; }
        if (mb > best1) { best1 = mb; vec1 = ib; }
    }

    // Merge the two chains: on ties, lower vec index wins (acc0 holds even k,
    // acc1 odd k, but compare indices explicitly to stay exact).
    float best = best0; int bestVec = vec0;
    if (best1 > best || (best1 == best && vec1 < bestVec)) { best = best1; bestVec = vec1; }

    // Warp reduction, min-index tie-break.
    #pragma unroll
    for (int off = 16; off > 0; off >>= 1) {
        const float ov = __shfl_down_sync(0xffffffffu, best, off);
        const int   oi = __shfl_down_sync(0xffffffffu, bestVec, off);
        if (ov > best || (ov == best && oi < bestVec)) { best = ov; bestVec = oi; }
    }

    __shared__ float sval[TPB / 32];
    __shared__ int   sidx[TPB / 32];
    const int lane = tid & 31;
    const int warp = tid >> 5;
    if (lane == 0) { sval[warp] = best; sidx[warp] = bestVec; }
    __syncthreads();

    if (tid == 0) {
        best = sval[0]; bestVec = sidx[0];
        #pragma unroll
        for (int w = 1; w < TPB / 32; ++w) {
            const float ov = sval[w];
            const int   oi = sidx[w];
            if (ov > best || (ov == best && oi < bestVec)) { best = ov; bestVec = oi; }
        }

        // Decode the component: lowest index equal to the max (first-index).
        const float4 v = m4[bestVec];
        int comp;
        if      (v.x == best) comp = 0;
        else if (v.y == best) comp = 1;
        else if (v.z == best) comp = 2;
        else                  comp = 3;
        const int bestIdx = (bestVec << 2) + comp;

        const int y = bestIdx >> 7;         // / 128
        const int x = bestIdx & (WW - 1);   // % 128

        // 5-point stencil, clamped == replicate ('edge') padding.
        const int xl = x > 0      ? x - 1 : 0;
        const int xr = x < WW - 1 ? x + 1 : WW - 1;
        const int yu = y > 0      ? y - 1 : 0;
        const int yd = y < HH - 1 ? y + 1 : HH - 1;

        const float c = best;
        const float l = m[y  * WW + xl];
        const float r = m[y  * WW + xr];
        const float u = m[yu * WW + x ];
        const float d = m[yd * WW + x ];

        const float den_x = l - 2.0f * c + r;
        const float den_y = u - 2.0f * c + d;
        const float dx = (den_x != 0.0f) ? 0.5f * (l - r) / den_x : 0.0f;
        const float dy = (den_y != 0.0f) ? 0.5f * (u - d) / den_y : 0.0f;

        out[map * 2 + 0] = (float)x + dx;
        out[map * 2 + 1] = (float)y + dy;
    }
}

extern "C" void kernel_launch(void* const* d_in, const int* in_sizes, int n_in,
                              void* d_out, int out_size)
{
    const float* in = (const float*)d_in[0];
    float* out = (float*)d_out;
    const int maps = in_sizes[0] / ELEMS_PER_MAP; // B*N = 2048
    spatial_argmax2d_kernel<<<maps, TPB>>>(in, out);
}

// round 3
// speedup vs baseline: 1.0115x; 1.0115x over previous
#include <cuda_runtime.h>
#include <math_constants.h>

// SpatialArgmax2d: per (B,N) 128x128 heatmap, argmax + sub-pixel parabolic fit.
// Input:  (B, N, H, W) fp32, B*N = 2048 maps of 16384 floats (64 KB each).
// Output: (B, N, 2) fp32 -> (x + dx, y + dy).
//
// Single-wave geometry: 2048 CTAs x 128 threads, __launch_bounds__(128,16)
// -> 16 CTAs/SM occupancy limit, so all 2048 CTAs (13.8/SM) are resident at
// once. No wave transition, minimal tail. Streaming (__ldcs) float4 loads,
// 32 per thread, two independent accumulator chains. First-index argmax
// semantics preserved exactly.

#define HH 128
#define WW 128
#define TPB 128
#define ELEMS_PER_MAP (HH * WW)              // 16384
#define VEC4_PER_MAP (ELEMS_PER_MAP / 4)     // 4096
#define VEC4_PER_THREAD (VEC4_PER_MAP / TPB) // 32

__global__ __launch_bounds__(TPB, 16) void spatial_argmax2d_kernel(
    const float* __restrict__ in, float* __restrict__ out)
{
    const int map = blockIdx.x;
    const float* __restrict__ m = in + (size_t)map * ELEMS_PER_MAP;
    const float4* __restrict__ m4 = reinterpret_cast<const float4*>(m);
    const int tid = threadIdx.x;

    // Two independent (value, vec-index) accumulators; strict '>' keeps the
    // earliest vec within each chain (k increases => i4 increases).
    float best0 = -CUDART_INF_F, best1 = -CUDART_INF_F;
    int   vec0  = 0,             vec1  = 0;

    #pragma unroll
    for (int k = 0; k < VEC4_PER_THREAD; k += 2) {
        const int ia = tid + k * TPB;
        const int ib = tid + (k + 1) * TPB;
        const float4 va = __ldcs(&m4[ia]);   // streaming: read-once data
        const float4 vb = __ldcs(&m4[ib]);
        const float ma = fmaxf(fmaxf(va.x, va.y), fmaxf(va.z, va.w));
        const float mb = fmaxf(fmaxf(vb.x, vb.y), fmaxf(vb.z, vb.w));
        if (ma > best0) { best0 = ma; vec0 = ia; }
        if (mb > best1) { best1 = mb; vec1 = ib; }
    }

    // Merge the two chains: ties resolved by lower vec index.
    float best = best0; int bestVec = vec0;
    if (best1 > best || (best1 == best && vec1 < bestVec)) { best = best1; bestVec = vec1; }

    // Warp reduction, min-index tie-break.
    #pragma unroll
    for (int off = 16; off > 0; off >>= 1) {
        const float ov = __shfl_down_sync(0xffffffffu, best, off);
        const int   oi = __shfl_down_sync(0xffffffffu, bestVec, off);
        if (ov > best || (ov == best && oi < bestVec)) { best = ov; bestVec = oi; }
    }

    __shared__ float sval[TPB / 32];
    __shared__ int   sidx[TPB / 32];
    const int lane = tid & 31;
    const int warp = tid >> 5;
    if (lane == 0) { sval[warp] = best; sidx[warp] = bestVec; }
    __syncthreads();

    if (tid == 0) {
        best = sval[0]; bestVec = sidx[0];
        #pragma unroll
        for (int w = 1; w < TPB / 32; ++w) {
            const float ov = sval[w];
            const int   oi = sidx[w];
            if (ov > best || (ov == best && oi < bestVec)) { best = ov; bestVec = oi; }
        }

        // Decode component: lowest index equal to the max (first-index).
        const float4 v = m4[bestVec];
        int comp;
        if      (v.x == best) comp = 0;
        else if (v.y == best) comp = 1;
        else if (v.z == best) comp = 2;
        else                  comp = 3;
        const int bestIdx = (bestVec << 2) + comp;

        const int y = bestIdx >> 7;         // / 128
        const int x = bestIdx & (WW - 1);   // % 128

        // 5-point stencil, clamped == replicate ('edge') padding.
        const int xl = x > 0      ? x - 1 : 0;
        const int xr = x < WW - 1 ? x + 1 : WW - 1;
        const int yu = y > 0      ? y - 1 : 0;
        const int yd = y < HH - 1 ? y + 1 : HH - 1;

        const float c = best;
        const float l = m[y  * WW + xl];
        const float r = m[y  * WW + xr];
        const float u = m[yu * WW + x ];
        const float d = m[yd * WW + x ];

        const float den_x = l - 2.0f * c + r;
        const float den_y = u - 2.0f * c + d;
        const float dx = (den_x != 0.0f) ? 0.5f * (l - r) / den_x : 0.0f;
        const float dy = (den_y != 0.0f) ? 0.5f * (u - d) / den_y : 0.0f;

        out[map * 2 + 0] = (float)x + dx;
        out[map * 2 + 1] = (float)y + dy;
    }
}

extern "C" void kernel_launch(void* const* d_in, const int* in_sizes, int n_in,
                              void* d_out, int out_size)
{
    const float* in = (const float*)d_in[0];
    float* out = (float*)d_out;
    const int maps = in_sizes[0] / ELEMS_PER_MAP; // B*N = 2048
    spatial_argmax2d_kernel<<<maps, TPB>>>(in, out);
}